// round 14
// baseline (speedup 1.0000x reference)
#include <cuda_runtime.h>

// Problem constants (fixed by the dataset)
#define NN 20000
#define EE 320000
#define DD 128
#define KK 8
#define HH 64
#define KHD 512   // K*H

typedef unsigned long long ull;
// packed fp32x2 helpers (sm_103a; PTX-only forms)
#define DUP2(o, f)  asm("mov.b64 %0, {%1, %1};" : "=l"(o) : "r"(__float_as_uint(f)))
#define FMA2(d, a, b, c) asm("fma.rn.f32x2 %0, %1, %2, %3;" : "=l"(d) : "l"(a), "l"(b), "l"(c))
#define MUL2(d, a, b) asm("mul.rn.f32x2 %0, %1, %2;" : "=l"(d) : "l"(a), "l"(b))
// cp.async helpers
#define CP_ASYNC16(s, g) asm volatile("cp.async.cg.shared.global [%0], [%1], 16;" :: "r"(s), "l"(g) : "memory")
#define CP_COMMIT()      asm volatile("cp.async.commit_group;" ::: "memory")
#define CP_WAIT0()       asm volatile("cp.async.wait_group 0;" ::: "memory")
#define CP_WAIT1()       asm volatile("cp.async.wait_group 1;" ::: "memory")

static __device__ __forceinline__ unsigned sm32(const void* p) {
    return (unsigned)__cvta_generic_to_shared(p);
}

// ---------------- scratch (__device__ globals; no allocations) -------------
// g_cnt, g_denom, g_ticket are zeroed at module load and re-zeroed during
// each run (node_kernel tail / last er block), so every replay is clean.
__device__ float g_x[(size_t)EE * DD];      // mean edge features (E,128)
__device__ float g_w[EE * KK];              // exp(leakyrelu(logit))
__device__ float g_er[NN * KK];             // node_feat @ W_r^T
__device__ float g_v[DD * KK];              // W_enc folded with attn_l
__device__ float g_denom[NN * KK];          // softmax denominators
__device__ float g_y[(size_t)NN * KK * DD]; // per-node weighted x sums (N,8,128)
__device__ int   g_cnt[NN];
__device__ int   g_off[NN];
__device__ int   g_cur[NN];
__device__ int   g_perm[EE];
__device__ int   g_ticket;

// ---------------- fused precompute: count + er(butterfly) + v + SCAN ------
// - every global thread counts one edge's dst (atomic)
// - warp w computes er for node blockIdx*8+w via the 9-shuffle butterfly
// - block 0 computes v[d,k]
// - LAST block to finish (ticket) performs the 20000-entry exclusive scan
//   and resets the ticket for the next graph replay.
__global__ __launch_bounds__(256) void er_count_scan_kernel(
        const float* __restrict__ nf,
        const float* __restrict__ W_r,
        const int* __restrict__ dst,
        const float* __restrict__ W_enc,
        const float* __restrict__ attn_l) {
    int tid = threadIdx.x;
    int gtid = blockIdx.x * blockDim.x + tid;
    if (gtid < EE) atomicAdd(&g_cnt[dst[gtid]], 1);

    if (blockIdx.x == 0) {
        for (int j = 0; j < 4; j++) {
            int i = tid * 4 + j;
            int d = i >> 3, k = i & 7;
            float s = 0.f;
            #pragma unroll 8
            for (int h = 0; h < HH; h++)
                s += W_enc[(size_t)d * KHD + k * HH + h] * attn_l[k * HH + h];
            g_v[d * KK + k] = s;
        }
    }

    // er via butterfly: lane holds W_r[k][4l..4l+3] for all 8 k
    {
        int lane = tid & 31;
        int w = tid >> 5;
        int n = blockIdx.x * 8 + w;          // 2500*8 = 20000 exact
        float4 wr[8];
        #pragma unroll
        for (int k = 0; k < 8; k++)
            wr[k] = *(const float4*)(W_r + k * DD + 4 * lane);
        float4 x = *(const float4*)(nf + (size_t)n * DD + 4 * lane);

        float a[8];
        #pragma unroll
        for (int k = 0; k < 8; k++)
            a[k] = x.x * wr[k].x + x.y * wr[k].y + x.z * wr[k].z + x.w * wr[k].w;

        int b4 = (lane >> 4) & 1, b3 = (lane >> 3) & 1, b2 = (lane >> 2) & 1;
        int myk = b4 * 4 + b3 * 2 + b2;
        #pragma unroll
        for (int j = 0; j < 4; j++) {
            float keep = b4 ? a[j + 4] : a[j];
            float send = b4 ? a[j] : a[j + 4];
            a[j] = keep + __shfl_xor_sync(0xffffffffu, send, 16);
        }
        #pragma unroll
        for (int j = 0; j < 2; j++) {
            float keep = b3 ? a[j + 2] : a[j];
            float send = b3 ? a[j] : a[j + 2];
            a[j] = keep + __shfl_xor_sync(0xffffffffu, send, 8);
        }
        {
            float keep = b2 ? a[1] : a[0];
            float send = b2 ? a[0] : a[1];
            a[0] = keep + __shfl_xor_sync(0xffffffffu, send, 4);
        }
        a[0] += __shfl_xor_sync(0xffffffffu, a[0], 2);
        a[0] += __shfl_xor_sync(0xffffffffu, a[0], 1);
        if ((lane & 3) == 0) g_er[n * KK + myk] = a[0];
    }

    // ---- last-block scan ----
    __threadfence();
    __shared__ int is_last;
    if (tid == 0) {
        int t = atomicAdd(&g_ticket, 1);
        is_last = (t == (int)gridDim.x - 1);
    }
    __syncthreads();
    if (!is_last) return;
    if (tid == 0) g_ticket = 0;             // reset for next graph replay

    __shared__ int s[256];
    const int CH = 79;                      // 256*79 = 20224 >= NN
    int start = tid * CH;
    int lsum = 0;
    for (int i = 0; i < CH; i++) {
        int idx = start + i;
        if (idx < NN) lsum += g_cnt[idx];
    }
    s[tid] = lsum;
    __syncthreads();
    for (int o = 1; o < 256; o <<= 1) {
        int v = (tid >= o) ? s[tid - o] : 0;
        __syncthreads();
        s[tid] += v;
        __syncthreads();
    }
    int run = s[tid] - lsum;
    for (int i = 0; i < CH; i++) {
        int idx = start + i;
        if (idx < NN) {
            g_off[idx] = run;
            g_cur[idx] = run;
            run += g_cnt[idx];
        }
    }
}

// ---------------- edge pass (warp-per-edge, one wave, ldcs, fused fill) ----
#define EDGE_GRID 1036
__global__ __launch_bounds__(128, 7) void edge_kernel(const float4* __restrict__ ef4,
                                                      const int* __restrict__ dst) {
    int lane = threadIdx.x & 31;
    int gw = (blockIdx.x * blockDim.x + threadIdx.x) >> 5;
    int nw = (gridDim.x * blockDim.x) >> 5;

    const float4* gv4 = (const float4*)g_v;
    float4 vv0[4], vv1[4];
    #pragma unroll
    for (int dd = 0; dd < 4; dd++) {
        vv0[dd] = gv4[(4 * lane + dd) * 2 + 0];
        vv1[dd] = gv4[(4 * lane + dd) * 2 + 1];
    }
    int b4 = (lane >> 4) & 1, b3 = (lane >> 3) & 1, b2 = (lane >> 2) & 1;
    int myk = b4 * 4 + b3 * 2 + b2;
    float4* gx4 = (float4*)g_x;
    const float inv3 = 1.0f / 3.0f;

    if (gw >= EE) return;
    const float4* base = ef4 + (size_t)gw * 96;
    float4 c0 = __ldcs(base + lane);
    float4 c1 = __ldcs(base + lane + 32);
    float4 c2 = __ldcs(base + lane + 64);
    int cnd = dst[gw];
    float cer = g_er[cnd * KK + myk];

    for (int e = gw; e < EE; e += nw) {
        int e2 = e + nw;
        int ep = (e2 < EE) ? e2 : e;
        const float4* nbase = ef4 + (size_t)ep * 96;
        float4 n0 = __ldcs(nbase + lane);
        float4 n1 = __ldcs(nbase + lane + 32);
        float4 n2 = __ldcs(nbase + lane + 64);
        int nnd = dst[ep];
        float ner = g_er[nnd * KK + myk];

        // fused CSR fill: one lane per edge claims a slot
        if (lane == 0) {
            int pos = atomicAdd(&g_cur[cnd], 1);
            g_perm[pos] = e;
        }

        float4 x;
        x.x = (c0.x + c1.x + c2.x) * inv3;
        x.y = (c0.y + c1.y + c2.y) * inv3;
        x.z = (c0.z + c1.z + c2.z) * inv3;
        x.w = (c0.w + c1.w + c2.w) * inv3;
        gx4[(size_t)e * 32 + lane] = x;

        float a[8];
        a[0] = x.x * vv0[0].x + x.y * vv0[1].x + x.z * vv0[2].x + x.w * vv0[3].x;
        a[1] = x.x * vv0[0].y + x.y * vv0[1].y + x.z * vv0[2].y + x.w * vv0[3].y;
        a[2] = x.x * vv0[0].z + x.y * vv0[1].z + x.z * vv0[2].z + x.w * vv0[3].z;
        a[3] = x.x * vv0[0].w + x.y * vv0[1].w + x.z * vv0[2].w + x.w * vv0[3].w;
        a[4] = x.x * vv1[0].x + x.y * vv1[1].x + x.z * vv1[2].x + x.w * vv1[3].x;
        a[5] = x.x * vv1[0].y + x.y * vv1[1].y + x.z * vv1[2].y + x.w * vv1[3].y;
        a[6] = x.x * vv1[0].z + x.y * vv1[1].z + x.z * vv1[2].z + x.w * vv1[3].z;
        a[7] = x.x * vv1[0].w + x.y * vv1[1].w + x.z * vv1[2].w + x.w * vv1[3].w;

        #pragma unroll
        for (int j = 0; j < 4; j++) {
            float keep = b4 ? a[j + 4] : a[j];
            float send = b4 ? a[j] : a[j + 4];
            a[j] = keep + __shfl_xor_sync(0xffffffffu, send, 16);
        }
        #pragma unroll
        for (int j = 0; j < 2; j++) {
            float keep = b3 ? a[j + 2] : a[j];
            float send = b3 ? a[j] : a[j + 2];
            a[j] = keep + __shfl_xor_sync(0xffffffffu, send, 8);
        }
        {
            float keep = b2 ? a[1] : a[0];
            float send = b2 ? a[0] : a[1];
            a[0] = keep + __shfl_xor_sync(0xffffffffu, send, 4);
        }
        a[0] += __shfl_xor_sync(0xffffffffu, a[0], 2);
        a[0] += __shfl_xor_sync(0xffffffffu, a[0], 1);

        if ((lane & 3) == 0) {
            float z = a[0] + cer;
            z = (z > 0.f) ? z : 0.01f * z;            // leaky relu
            float wv = __expf(z);                     // shift-free softmax weight
            g_w[e * KK + myk] = wv;
            atomicAdd(&g_denom[cnd * KK + myk], wv);
        }

        c0 = n0; c1 = n1; c2 = n2; cnd = nnd; cer = ner;
    }
}

// ---------------- per-node aggregation: warp-per-node + cp.async batches ---
// (unchanged from R13 — 51.5 us, DRAM 58.5%)
__global__ __launch_bounds__(128) void node_kernel() {
    __shared__ __align__(16) float xbuf[4][2][8][128];  // 32 KB
    __shared__ __align__(16) float wbuf[4][2][8][8];    //  2 KB
    int wid = threadIdx.x >> 5;
    int lane = threadIdx.x & 31;
    int n = blockIdx.x * 4 + wid;

    int deg = g_cnt[n];
    int off = g_off[n];
    int nb = (deg + 7) >> 3;

    ull acc[8][2];
    #pragma unroll
    for (int k = 0; k < 8; k++) { acc[k][0] = 0ull; acc[k][1] = 0ull; }

    if (deg > 0) {
        auto issue = [&](int b, int buf) {
            int base = b * 8;
            int cnt = deg - base; if (cnt > 8) cnt = 8;
            int pe = g_perm[off + base + min(lane & 7, cnt - 1)];
            int ej[8];
            #pragma unroll
            for (int j = 0; j < 8; j++) {
                int jj = (j < cnt) ? j : (cnt - 1);
                ej[j] = __shfl_sync(0xffffffffu, pe, jj);
            }
            #pragma unroll
            for (int j = 0; j < 8; j++) {
                unsigned s = sm32(&xbuf[wid][buf][j][lane * 4]);
                const float* g = g_x + (size_t)ej[j] * DD + lane * 4;
                CP_ASYNC16(s, g);
            }
            if (lane < 16) {
                int j = lane >> 1;
                unsigned s = sm32(&wbuf[wid][buf][j][(lane & 1) * 4]);
                const float* g = g_w + (size_t)ej[j] * KK + (lane & 1) * 4;
                CP_ASYNC16(s, g);
            }
            CP_COMMIT();
        };

        issue(0, 0);
        if (nb > 1) issue(1, 1);

        for (int b = 0; b < nb; b++) {
            if (b + 1 < nb) { CP_WAIT1(); } else { CP_WAIT0(); }
            __syncwarp();
            int buf = b & 1;
            int base = b * 8;
            int cnt = deg - base; if (cnt > 8) cnt = 8;
            for (int j = 0; j < cnt; j++) {
                const float4* wrow = (const float4*)&wbuf[wid][buf][j][0];
                float4 wa = wrow[0], wb = wrow[1];
                ulonglong2 xd = *(const ulonglong2*)&xbuf[wid][buf][j][lane * 4];
                ull w2;
                DUP2(w2, wa.x); FMA2(acc[0][0], xd.x, w2, acc[0][0]); FMA2(acc[0][1], xd.y, w2, acc[0][1]);
                DUP2(w2, wa.y); FMA2(acc[1][0], xd.x, w2, acc[1][0]); FMA2(acc[1][1], xd.y, w2, acc[1][1]);
                DUP2(w2, wa.z); FMA2(acc[2][0], xd.x, w2, acc[2][0]); FMA2(acc[2][1], xd.y, w2, acc[2][1]);
                DUP2(w2, wa.w); FMA2(acc[3][0], xd.x, w2, acc[3][0]); FMA2(acc[3][1], xd.y, w2, acc[3][1]);
                DUP2(w2, wb.x); FMA2(acc[4][0], xd.x, w2, acc[4][0]); FMA2(acc[4][1], xd.y, w2, acc[4][1]);
                DUP2(w2, wb.y); FMA2(acc[5][0], xd.x, w2, acc[5][0]); FMA2(acc[5][1], xd.y, w2, acc[5][1]);
                DUP2(w2, wb.z); FMA2(acc[6][0], xd.x, w2, acc[6][0]); FMA2(acc[6][1], xd.y, w2, acc[6][1]);
                DUP2(w2, wb.w); FMA2(acc[7][0], xd.x, w2, acc[7][0]); FMA2(acc[7][1], xd.y, w2, acc[7][1]);
            }
            if (b + 2 < nb) {
                __syncwarp();
                issue(b + 2, buf);
            }
        }
    }

    const float4* dn4 = (const float4*)(g_denom + n * KK);
    float4 d0 = dn4[0], d1 = dn4[1];
    float inv[8];
    inv[0] = (deg > 0) ? __frcp_rn(d0.x) : 0.f;
    inv[1] = (deg > 0) ? __frcp_rn(d0.y) : 0.f;
    inv[2] = (deg > 0) ? __frcp_rn(d0.z) : 0.f;
    inv[3] = (deg > 0) ? __frcp_rn(d0.w) : 0.f;
    inv[4] = (deg > 0) ? __frcp_rn(d1.x) : 0.f;
    inv[5] = (deg > 0) ? __frcp_rn(d1.y) : 0.f;
    inv[6] = (deg > 0) ? __frcp_rn(d1.z) : 0.f;
    inv[7] = (deg > 0) ? __frcp_rn(d1.w) : 0.f;

    ulonglong2* gy2 = (ulonglong2*)g_y;
    #pragma unroll
    for (int k = 0; k < 8; k++) {
        ull iv;
        DUP2(iv, inv[k]);
        ulonglong2 o;
        MUL2(o.x, acc[k][0], iv);
        MUL2(o.y, acc[k][1], iv);
        gy2[(size_t)n * 256 + k * 32 + lane] = o;
    }

    __syncwarp();
    if (lane == 0) g_cnt[n] = 0;
    if (lane < KK) g_denom[n * KK + lane] = 0.f;
}

// ---------------- block-diagonal GEMM with packed f32x2 FMA ----------------
// (unchanged — now in the PROFILED slot)
__global__ __launch_bounds__(256) void out_kernel(const float* __restrict__ W_enc,
                                                  float* __restrict__ out) {
    __shared__ float As[32][130];
    __shared__ float Ws[32][65];
    int k = blockIdx.y;
    int n0 = blockIdx.x * 128;
    int tid = threadIdx.x;
    int tx = tid & 15, ty = tid >> 4;
    int ty8 = ty * 8, tx4 = tx * 4;

    ull c[4][4];
    #pragma unroll
    for (int j = 0; j < 4; j++)
        #pragma unroll
        for (int cc = 0; cc < 4; cc++) c[j][cc] = 0ull;

    for (int kk = 0; kk < DD; kk += 32) {
        #pragma unroll
        for (int p = 0; p < 16; p++) {
            int q = tid + 256 * p;
            int row = q >> 5, d = q & 31;
            int n = n0 + row;
            As[d][row] = (n < NN) ? g_y[(size_t)n * (KK * DD) + k * DD + kk + d] : 0.f;
        }
        #pragma unroll
        for (int p = 0; p < 8; p++) {
            int q = tid + 256 * p;
            int d = q >> 6, h = q & 63;
            Ws[d][h] = W_enc[(size_t)(kk + d) * KHD + k * HH + h];
        }
        __syncthreads();
        #pragma unroll
        for (int d = 0; d < 32; d++) {
            ull a[4];
            a[0] = *(const ull*)&As[d][ty8];
            a[1] = *(const ull*)&As[d][ty8 + 2];
            a[2] = *(const ull*)&As[d][ty8 + 4];
            a[3] = *(const ull*)&As[d][ty8 + 6];
            #pragma unroll
            for (int cc = 0; cc < 4; cc++) {
                ull bb;
                DUP2(bb, Ws[d][tx4 + cc]);
                FMA2(c[0][cc], a[0], bb, c[0][cc]);
                FMA2(c[1][cc], a[1], bb, c[1][cc]);
                FMA2(c[2][cc], a[2], bb, c[2][cc]);
                FMA2(c[3][cc], a[3], bb, c[3][cc]);
            }
        }
        __syncthreads();
    }
    #pragma unroll
    for (int j = 0; j < 4; j++) {
        int r0 = n0 + ty8 + 2 * j;
        #pragma unroll
        for (int cc = 0; cc < 4; cc++) {
            unsigned int lo, hi;
            asm("mov.b64 {%0, %1}, %2;" : "=r"(lo), "=r"(hi) : "l"(c[j][cc]));
            if (r0 < NN)
                out[(size_t)r0 * KHD + k * HH + tx4 + cc] = __uint_as_float(lo);
            if (r0 + 1 < NN)
                out[(size_t)(r0 + 1) * KHD + k * HH + tx4 + cc] = __uint_as_float(hi);
        }
    }
}

// ---------------- launch ----------------------------------------------------
// 4 launches total -> out_kernel sits at index 3 and is the profiled one.
extern "C" void kernel_launch(void* const* d_in, const int* in_sizes, int n_in,
                              void* d_out, int out_size) {
    const float* node_feat = (const float*)d_in[0]; // (N,128)
    const float* edge_feat = (const float*)d_in[1]; // (E,3,128)
    const float* W_enc     = (const float*)d_in[2]; // (128,512)
    const float* attn_l    = (const float*)d_in[3]; // (1,8,64)
    const float* W_r       = (const float*)d_in[4]; // (8,128)
    const int*   dst       = (const int*)d_in[5];   // (E,)
    float* out = (float*)d_out;                     // (N,8,64)

    er_count_scan_kernel<<<NN / 8, 256>>>(node_feat, W_r, dst, W_enc, attn_l); // 0
    edge_kernel<<<EDGE_GRID, 128>>>((const float4*)edge_feat, dst);            // 1
    node_kernel<<<NN / 4, 128>>>();                                            // 2
    out_kernel<<<dim3((NN + 127) / 128, 8), 256>>>(W_enc, out);                // 3 <- profiled
}

// round 16
// speedup vs baseline: 1.0219x; 1.0219x over previous
#include <cuda_runtime.h>

// Problem constants (fixed by the dataset)
#define NN 20000
#define EE 320000
#define DD 128
#define KK 8
#define HH 64
#define KHD 512   // K*H

typedef unsigned long long ull;
// packed fp32x2 helpers (sm_103a; PTX-only forms)
#define DUP2(o, f)  asm("mov.b64 %0, {%1, %1};" : "=l"(o) : "r"(__float_as_uint(f)))
#define FMA2(d, a, b, c) asm("fma.rn.f32x2 %0, %1, %2, %3;" : "=l"(d) : "l"(a), "l"(b), "l"(c))
#define MUL2(d, a, b) asm("mul.rn.f32x2 %0, %1, %2;" : "=l"(d) : "l"(a), "l"(b))
// cp.async helpers
#define CP_ASYNC16(s, g) asm volatile("cp.async.cg.shared.global [%0], [%1], 16;" :: "r"(s), "l"(g) : "memory")
#define CP_COMMIT()      asm volatile("cp.async.commit_group;" ::: "memory")
#define CP_WAIT0()       asm volatile("cp.async.wait_group 0;" ::: "memory")
#define CP_WAIT1()       asm volatile("cp.async.wait_group 1;" ::: "memory")

static __device__ __forceinline__ unsigned sm32(const void* p) {
    return (unsigned)__cvta_generic_to_shared(p);
}

// ---------------- scratch (__device__ globals; no allocations) -------------
// g_cnt, g_denom, g_ticket are zeroed at module load and re-zeroed during
// each run (node_kernel tail / last er block), so every replay is clean.
__device__ float g_x[(size_t)EE * DD];      // mean edge features (E,128)
__device__ float g_w[EE * KK];              // exp(leakyrelu(logit))
__device__ float g_er[NN * KK];             // node_feat @ W_r^T
__device__ float g_v[DD * KK];              // W_enc folded with attn_l
__device__ float g_denom[NN * KK];          // softmax denominators
__device__ float g_y[(size_t)NN * KK * DD]; // per-node weighted x sums (N,8,128)
__device__ int   g_cnt[NN];
__device__ int   g_off[NN];
__device__ int   g_cur[NN];
__device__ int   g_perm[EE];
__device__ int   g_ticket;

// ---------------- fused precompute: count + er(butterfly) + v + SCAN ------
// 1024-thread blocks, grid 625. Warp w computes er for node blockIdx*32+w.
// LAST block (ticket) performs the 20000-entry exclusive scan with the
// proven 1024x20 layout, then resets the ticket for the next replay.
__global__ __launch_bounds__(1024) void er_count_scan_kernel(
        const float* __restrict__ nf,
        const float* __restrict__ W_r,
        const int* __restrict__ dst,
        const float* __restrict__ W_enc,
        const float* __restrict__ attn_l) {
    int tid = threadIdx.x;
    int gtid = blockIdx.x * blockDim.x + tid;
    if (gtid < EE) atomicAdd(&g_cnt[dst[gtid]], 1);

    if (blockIdx.x == 0) {
        // 1024 threads = 128*8 entries of v, one each
        int d = tid >> 3, k = tid & 7;
        float s = 0.f;
        #pragma unroll 8
        for (int h = 0; h < HH; h++)
            s += W_enc[(size_t)d * KHD + k * HH + h] * attn_l[k * HH + h];
        g_v[d * KK + k] = s;
    }

    // er via butterfly: lane holds W_r[k][4l..4l+3] for all 8 k
    {
        int lane = tid & 31;
        int w = tid >> 5;                    // 0..31
        int n = blockIdx.x * 32 + w;         // 625*32 = 20000 exact
        float4 wr[8];
        #pragma unroll
        for (int k = 0; k < 8; k++)
            wr[k] = *(const float4*)(W_r + k * DD + 4 * lane);
        float4 x = *(const float4*)(nf + (size_t)n * DD + 4 * lane);

        float a[8];
        #pragma unroll
        for (int k = 0; k < 8; k++)
            a[k] = x.x * wr[k].x + x.y * wr[k].y + x.z * wr[k].z + x.w * wr[k].w;

        int b4 = (lane >> 4) & 1, b3 = (lane >> 3) & 1, b2 = (lane >> 2) & 1;
        int myk = b4 * 4 + b3 * 2 + b2;
        #pragma unroll
        for (int j = 0; j < 4; j++) {
            float keep = b4 ? a[j + 4] : a[j];
            float send = b4 ? a[j] : a[j + 4];
            a[j] = keep + __shfl_xor_sync(0xffffffffu, send, 16);
        }
        #pragma unroll
        for (int j = 0; j < 2; j++) {
            float keep = b3 ? a[j + 2] : a[j];
            float send = b3 ? a[j] : a[j + 2];
            a[j] = keep + __shfl_xor_sync(0xffffffffu, send, 8);
        }
        {
            float keep = b2 ? a[1] : a[0];
            float send = b2 ? a[0] : a[1];
            a[0] = keep + __shfl_xor_sync(0xffffffffu, send, 4);
        }
        a[0] += __shfl_xor_sync(0xffffffffu, a[0], 2);
        a[0] += __shfl_xor_sync(0xffffffffu, a[0], 1);
        if ((lane & 3) == 0) g_er[n * KK + myk] = a[0];
    }

    // ---- last-block scan (1024 threads x 20 chunk) ----
    __threadfence();
    __shared__ int is_last;
    if (tid == 0) {
        int t = atomicAdd(&g_ticket, 1);
        is_last = (t == (int)gridDim.x - 1);
    }
    __syncthreads();
    if (!is_last) return;
    if (tid == 0) g_ticket = 0;             // reset for next graph replay

    __shared__ int s[1024];
    const int CH = 20;                      // 1024*20 = 20480 >= NN
    int start = tid * CH;
    int lsum = 0;
    for (int i = 0; i < CH; i++) {
        int idx = start + i;
        if (idx < NN) lsum += g_cnt[idx];
    }
    s[tid] = lsum;
    __syncthreads();
    for (int o = 1; o < 1024; o <<= 1) {
        int v = (tid >= o) ? s[tid - o] : 0;
        __syncthreads();
        s[tid] += v;
        __syncthreads();
    }
    int run = s[tid] - lsum;
    for (int i = 0; i < CH; i++) {
        int idx = start + i;
        if (idx < NN) {
            g_off[idx] = run;
            g_cur[idx] = run;
            run += g_cnt[idx];
        }
    }
}

// ---------------- edge pass (warp-per-edge, one wave, ldcs, fused fill) ----
#define EDGE_GRID 1036
__global__ __launch_bounds__(128, 7) void edge_kernel(const float4* __restrict__ ef4,
                                                      const int* __restrict__ dst) {
    int lane = threadIdx.x & 31;
    int gw = (blockIdx.x * blockDim.x + threadIdx.x) >> 5;
    int nw = (gridDim.x * blockDim.x) >> 5;

    const float4* gv4 = (const float4*)g_v;
    float4 vv0[4], vv1[4];
    #pragma unroll
    for (int dd = 0; dd < 4; dd++) {
        vv0[dd] = gv4[(4 * lane + dd) * 2 + 0];
        vv1[dd] = gv4[(4 * lane + dd) * 2 + 1];
    }
    int b4 = (lane >> 4) & 1, b3 = (lane >> 3) & 1, b2 = (lane >> 2) & 1;
    int myk = b4 * 4 + b3 * 2 + b2;
    float4* gx4 = (float4*)g_x;
    const float inv3 = 1.0f / 3.0f;

    if (gw >= EE) return;
    const float4* base = ef4 + (size_t)gw * 96;
    float4 c0 = __ldcs(base + lane);
    float4 c1 = __ldcs(base + lane + 32);
    float4 c2 = __ldcs(base + lane + 64);
    int cnd = dst[gw];
    float cer = g_er[cnd * KK + myk];

    for (int e = gw; e < EE; e += nw) {
        int e2 = e + nw;
        int ep = (e2 < EE) ? e2 : e;
        const float4* nbase = ef4 + (size_t)ep * 96;
        float4 n0 = __ldcs(nbase + lane);
        float4 n1 = __ldcs(nbase + lane + 32);
        float4 n2 = __ldcs(nbase + lane + 64);
        int nnd = dst[ep];
        float ner = g_er[nnd * KK + myk];

        // fused CSR fill: one lane per edge claims a slot
        if (lane == 0) {
            int pos = atomicAdd(&g_cur[cnd], 1);
            g_perm[pos] = e;
        }

        float4 x;
        x.x = (c0.x + c1.x + c2.x) * inv3;
        x.y = (c0.y + c1.y + c2.y) * inv3;
        x.z = (c0.z + c1.z + c2.z) * inv3;
        x.w = (c0.w + c1.w + c2.w) * inv3;
        gx4[(size_t)e * 32 + lane] = x;

        float a[8];
        a[0] = x.x * vv0[0].x + x.y * vv0[1].x + x.z * vv0[2].x + x.w * vv0[3].x;
        a[1] = x.x * vv0[0].y + x.y * vv0[1].y + x.z * vv0[2].y + x.w * vv0[3].y;
        a[2] = x.x * vv0[0].z + x.y * vv0[1].z + x.z * vv0[2].z + x.w * vv0[3].z;
        a[3] = x.x * vv0[0].w + x.y * vv0[1].w + x.z * vv0[2].w + x.w * vv0[3].w;
        a[4] = x.x * vv1[0].x + x.y * vv1[1].x + x.z * vv1[2].x + x.w * vv1[3].x;
        a[5] = x.x * vv1[0].y + x.y * vv1[1].y + x.z * vv1[2].y + x.w * vv1[3].y;
        a[6] = x.x * vv1[0].z + x.y * vv1[1].z + x.z * vv1[2].z + x.w * vv1[3].z;
        a[7] = x.x * vv1[0].w + x.y * vv1[1].w + x.z * vv1[2].w + x.w * vv1[3].w;

        #pragma unroll
        for (int j = 0; j < 4; j++) {
            float keep = b4 ? a[j + 4] : a[j];
            float send = b4 ? a[j] : a[j + 4];
            a[j] = keep + __shfl_xor_sync(0xffffffffu, send, 16);
        }
        #pragma unroll
        for (int j = 0; j < 2; j++) {
            float keep = b3 ? a[j + 2] : a[j];
            float send = b3 ? a[j] : a[j + 2];
            a[j] = keep + __shfl_xor_sync(0xffffffffu, send, 8);
        }
        {
            float keep = b2 ? a[1] : a[0];
            float send = b2 ? a[0] : a[1];
            a[0] = keep + __shfl_xor_sync(0xffffffffu, send, 4);
        }
        a[0] += __shfl_xor_sync(0xffffffffu, a[0], 2);
        a[0] += __shfl_xor_sync(0xffffffffu, a[0], 1);

        if ((lane & 3) == 0) {
            float z = a[0] + cer;
            z = (z > 0.f) ? z : 0.01f * z;            // leaky relu
            float wv = __expf(z);                     // shift-free softmax weight
            g_w[e * KK + myk] = wv;
            atomicAdd(&g_denom[cnd * KK + myk], wv);
        }

        c0 = n0; c1 = n1; c2 = n2; cnd = nnd; cer = ner;
    }
}

// ---------------- per-node aggregation: warp-per-node + cp.async batches ---
// (unchanged from R13 — 51.5 us, DRAM 58.5%)
__global__ __launch_bounds__(128) void node_kernel() {
    __shared__ __align__(16) float xbuf[4][2][8][128];  // 32 KB
    __shared__ __align__(16) float wbuf[4][2][8][8];    //  2 KB
    int wid = threadIdx.x >> 5;
    int lane = threadIdx.x & 31;
    int n = blockIdx.x * 4 + wid;

    int deg = g_cnt[n];
    int off = g_off[n];
    int nb = (deg + 7) >> 3;

    ull acc[8][2];
    #pragma unroll
    for (int k = 0; k < 8; k++) { acc[k][0] = 0ull; acc[k][1] = 0ull; }

    if (deg > 0) {
        auto issue = [&](int b, int buf) {
            int base = b * 8;
            int cnt = deg - base; if (cnt > 8) cnt = 8;
            int pe = g_perm[off + base + min(lane & 7, cnt - 1)];
            int ej[8];
            #pragma unroll
            for (int j = 0; j < 8; j++) {
                int jj = (j < cnt) ? j : (cnt - 1);
                ej[j] = __shfl_sync(0xffffffffu, pe, jj);
            }
            #pragma unroll
            for (int j = 0; j < 8; j++) {
                unsigned s = sm32(&xbuf[wid][buf][j][lane * 4]);
                const float* g = g_x + (size_t)ej[j] * DD + lane * 4;
                CP_ASYNC16(s, g);
            }
            if (lane < 16) {
                int j = lane >> 1;
                unsigned s = sm32(&wbuf[wid][buf][j][(lane & 1) * 4]);
                const float* g = g_w + (size_t)ej[j] * KK + (lane & 1) * 4;
                CP_ASYNC16(s, g);
            }
            CP_COMMIT();
        };

        issue(0, 0);
        if (nb > 1) issue(1, 1);

        for (int b = 0; b < nb; b++) {
            if (b + 1 < nb) { CP_WAIT1(); } else { CP_WAIT0(); }
            __syncwarp();
            int buf = b & 1;
            int base = b * 8;
            int cnt = deg - base; if (cnt > 8) cnt = 8;
            for (int j = 0; j < cnt; j++) {
                const float4* wrow = (const float4*)&wbuf[wid][buf][j][0];
                float4 wa = wrow[0], wb = wrow[1];
                ulonglong2 xd = *(const ulonglong2*)&xbuf[wid][buf][j][lane * 4];
                ull w2;
                DUP2(w2, wa.x); FMA2(acc[0][0], xd.x, w2, acc[0][0]); FMA2(acc[0][1], xd.y, w2, acc[0][1]);
                DUP2(w2, wa.y); FMA2(acc[1][0], xd.x, w2, acc[1][0]); FMA2(acc[1][1], xd.y, w2, acc[1][1]);
                DUP2(w2, wa.z); FMA2(acc[2][0], xd.x, w2, acc[2][0]); FMA2(acc[2][1], xd.y, w2, acc[2][1]);
                DUP2(w2, wa.w); FMA2(acc[3][0], xd.x, w2, acc[3][0]); FMA2(acc[3][1], xd.y, w2, acc[3][1]);
                DUP2(w2, wb.x); FMA2(acc[4][0], xd.x, w2, acc[4][0]); FMA2(acc[4][1], xd.y, w2, acc[4][1]);
                DUP2(w2, wb.y); FMA2(acc[5][0], xd.x, w2, acc[5][0]); FMA2(acc[5][1], xd.y, w2, acc[5][1]);
                DUP2(w2, wb.z); FMA2(acc[6][0], xd.x, w2, acc[6][0]); FMA2(acc[6][1], xd.y, w2, acc[6][1]);
                DUP2(w2, wb.w); FMA2(acc[7][0], xd.x, w2, acc[7][0]); FMA2(acc[7][1], xd.y, w2, acc[7][1]);
            }
            if (b + 2 < nb) {
                __syncwarp();
                issue(b + 2, buf);
            }
        }
    }

    const float4* dn4 = (const float4*)(g_denom + n * KK);
    float4 d0 = dn4[0], d1 = dn4[1];
    float inv[8];
    inv[0] = (deg > 0) ? __frcp_rn(d0.x) : 0.f;
    inv[1] = (deg > 0) ? __frcp_rn(d0.y) : 0.f;
    inv[2] = (deg > 0) ? __frcp_rn(d0.z) : 0.f;
    inv[3] = (deg > 0) ? __frcp_rn(d0.w) : 0.f;
    inv[4] = (deg > 0) ? __frcp_rn(d1.x) : 0.f;
    inv[5] = (deg > 0) ? __frcp_rn(d1.y) : 0.f;
    inv[6] = (deg > 0) ? __frcp_rn(d1.z) : 0.f;
    inv[7] = (deg > 0) ? __frcp_rn(d1.w) : 0.f;

    ulonglong2* gy2 = (ulonglong2*)g_y;
    #pragma unroll
    for (int k = 0; k < 8; k++) {
        ull iv;
        DUP2(iv, inv[k]);
        ulonglong2 o;
        MUL2(o.x, acc[k][0], iv);
        MUL2(o.y, acc[k][1], iv);
        gy2[(size_t)n * 256 + k * 32 + lane] = o;
    }

    __syncwarp();
    if (lane == 0) g_cnt[n] = 0;
    if (lane < KK) g_denom[n * KK + lane] = 0.f;
}

// ---------------- block-diagonal GEMM with packed f32x2 FMA ----------------
// Changes vs R14: Ws padded to 68 (16B-aligned rows) and read as ONE LDS.128
// per cc-group instead of 4 scalar LDS; __launch_bounds__(256,3) raises
// residency from 2 to 3 blocks/SM.
__global__ __launch_bounds__(256, 3) void out_kernel(const float* __restrict__ W_enc,
                                                     float* __restrict__ out) {
    __shared__ float As[32][130];   // [d][row], 130 pad: 8B-aligned rows
    __shared__ __align__(16) float Ws[32][68];   // 272B rows, 16B-aligned
    int k = blockIdx.y;
    int n0 = blockIdx.x * 128;
    int tid = threadIdx.x;
    int tx = tid & 15, ty = tid >> 4;
    int ty8 = ty * 8, tx4 = tx * 4;

    ull c[4][4];
    #pragma unroll
    for (int j = 0; j < 4; j++)
        #pragma unroll
        for (int cc = 0; cc < 4; cc++) c[j][cc] = 0ull;

    for (int kk = 0; kk < DD; kk += 32) {
        #pragma unroll
        for (int p = 0; p < 16; p++) {
            int q = tid + 256 * p;
            int row = q >> 5, d = q & 31;
            int n = n0 + row;
            As[d][row] = (n < NN) ? g_y[(size_t)n * (KK * DD) + k * DD + kk + d] : 0.f;
        }
        #pragma unroll
        for (int p = 0; p < 8; p++) {
            int q = tid + 256 * p;
            int d = q >> 6, h = q & 63;
            Ws[d][h] = W_enc[(size_t)(kk + d) * KHD + k * HH + h];
        }
        __syncthreads();
        #pragma unroll
        for (int d = 0; d < 32; d++) {
            ull a[4];
            a[0] = *(const ull*)&As[d][ty8];
            a[1] = *(const ull*)&As[d][ty8 + 2];
            a[2] = *(const ull*)&As[d][ty8 + 4];
            a[3] = *(const ull*)&As[d][ty8 + 6];
            float4 bv = *(const float4*)&Ws[d][tx4];   // one LDS.128
            const float bs[4] = {bv.x, bv.y, bv.z, bv.w};
            #pragma unroll
            for (int cc = 0; cc < 4; cc++) {
                ull bb;
                DUP2(bb, bs[cc]);
                FMA2(c[0][cc], a[0], bb, c[0][cc]);
                FMA2(c[1][cc], a[1], bb, c[1][cc]);
                FMA2(c[2][cc], a[2], bb, c[2][cc]);
                FMA2(c[3][cc], a[3], bb, c[3][cc]);
            }
        }
        __syncthreads();
    }
    #pragma unroll
    for (int j = 0; j < 4; j++) {
        int r0 = n0 + ty8 + 2 * j;
        #pragma unroll
        for (int cc = 0; cc < 4; cc++) {
            unsigned int lo, hi;
            asm("mov.b64 {%0, %1}, %2;" : "=r"(lo), "=r"(hi) : "l"(c[j][cc]));
            if (r0 < NN)
                out[(size_t)r0 * KHD + k * HH + tx4 + cc] = __uint_as_float(lo);
            if (r0 + 1 < NN)
                out[(size_t)(r0 + 1) * KHD + k * HH + tx4 + cc] = __uint_as_float(hi);
        }
    }
}

// ---------------- launch ----------------------------------------------------
// 4 launches total -> out_kernel sits at index 3 and is the profiled one.
extern "C" void kernel_launch(void* const* d_in, const int* in_sizes, int n_in,
                              void* d_out, int out_size) {
    const float* node_feat = (const float*)d_in[0]; // (N,128)
    const float* edge_feat = (const float*)d_in[1]; // (E,3,128)
    const float* W_enc     = (const float*)d_in[2]; // (128,512)
    const float* attn_l    = (const float*)d_in[3]; // (1,8,64)
    const float* W_r       = (const float*)d_in[4]; // (8,128)
    const int*   dst       = (const int*)d_in[5];   // (E,)
    float* out = (float*)d_out;                     // (N,8,64)

    er_count_scan_kernel<<<NN / 32, 1024>>>(node_feat, W_r, dst, W_enc, attn_l); // 0
    edge_kernel<<<EDGE_GRID, 128>>>((const float4*)edge_feat, dst);              // 1
    node_kernel<<<NN / 4, 128>>>();                                              // 2
    out_kernel<<<dim3((NN + 127) / 128, 8), 256>>>(W_enc, out);                  // 3 <- profiled
}